// round 2
// baseline (speedup 1.0000x reference)
#include <cuda_runtime.h>
#include <cstdint>

#define L_DIM 2048
#define B_DIM 64
#define D_DEC 1024
#define D_ALIGN 512
#define D_ENC 1024
#define N_SPLIT 16           // L splits for attend partials
#define L_PER_SPLIT (L_DIM / N_SPLIT)   // 128

// ---- scratch (no allocations allowed) ----
__device__ float g_proj[B_DIM * D_ALIGN];            // 128 KB
__device__ float g_score[L_DIM * B_DIM];             // 512 KB
__device__ float g_partial[N_SPLIT * B_DIM * D_ENC]; // 4 MB

__device__ __forceinline__ float fast_tanh(float x) {
    // tanh(x) = 1 - 2/(exp(2x)+1); __expf is MUFU.EX2-based, ~1e-6 rel err
    float e = __expf(2.0f * x);
    float r;
    asm("rcp.approx.f32 %0, %1;" : "=f"(r) : "f"(e + 1.0f));
    return fmaf(-2.0f, r, 1.0f);
}

// ---- Kernel 1: proj[b,a] = dot(s_tm1[b,:], sa_w[a,:]) + sa_b[a] ----
// one warp per (b,a); grid = 64*512/8 = 4096 blocks of 256 threads
__global__ __launch_bounds__(256) void k_proj(const float* __restrict__ s_tm1,
                                              const float* __restrict__ sa_w,
                                              const float* __restrict__ sa_b) {
    int gw = blockIdx.x * 8 + (threadIdx.x >> 5);
    int b = gw >> 9;          // /512
    int a = gw & 511;
    int lane = threadIdx.x & 31;
    const float4* wr = (const float4*)(sa_w + (size_t)a * D_DEC);
    const float4* sr = (const float4*)(s_tm1 + (size_t)b * D_DEC);
    float sum = 0.0f;
#pragma unroll
    for (int it = 0; it < 8; it++) {
        float4 w4 = wr[lane + it * 32];
        float4 s4 = sr[lane + it * 32];
        sum = fmaf(w4.x, s4.x, sum);
        sum = fmaf(w4.y, s4.y, sum);
        sum = fmaf(w4.z, s4.z, sum);
        sum = fmaf(w4.w, s4.w, sum);
    }
#pragma unroll
    for (int o = 16; o > 0; o >>= 1) sum += __shfl_xor_sync(0xFFFFFFFFu, sum, o);
    if (lane == 0) g_proj[b * D_ALIGN + a] = sum + sa_b[a];
}

// ---- Kernel 2: score[l,b] = sum_a tanh(proj[b,a]+uh[l,b,a])*a1_w[a] + a1_b ----
// grid (L/8, B); block = 8 warps, warp w handles l = tile*8+w; shared proj row + weights
__global__ __launch_bounds__(256) void k_score(const float* __restrict__ uh,
                                               const float* __restrict__ a1_w,
                                               const float* __restrict__ a1_b) {
    __shared__ float4 s_proj[D_ALIGN / 4];
    __shared__ float4 s_w[D_ALIGN / 4];
    int b = blockIdx.y;
    for (int i = threadIdx.x; i < D_ALIGN / 4; i += 256) {
        s_proj[i] = ((const float4*)(g_proj + b * D_ALIGN))[i];
        s_w[i] = ((const float4*)a1_w)[i];
    }
    __syncthreads();
    int warp = threadIdx.x >> 5, lane = threadIdx.x & 31;
    int l = blockIdx.x * 8 + warp;
    const float4* row = (const float4*)(uh + ((size_t)(l * B_DIM + b)) * D_ALIGN);
    float sum = 0.0f;
#pragma unroll
    for (int it = 0; it < 4; it++) {
        int a4 = lane + it * 32;
        float4 u = row[a4];
        float4 p = s_proj[a4];
        float4 w = s_w[a4];
        sum = fmaf(fast_tanh(p.x + u.x), w.x, sum);
        sum = fmaf(fast_tanh(p.y + u.y), w.y, sum);
        sum = fmaf(fast_tanh(p.z + u.z), w.z, sum);
        sum = fmaf(fast_tanh(p.w + u.w), w.w, sum);
    }
#pragma unroll
    for (int o = 16; o > 0; o >>= 1) sum += __shfl_xor_sync(0xFFFFFFFFu, sum, o);
    if (lane == 0) g_score[l * B_DIM + b] = sum + a1_b[0];
}

// ---- Kernel 3: masked softmax over L per column b; writes e_ij to out[0:L*B] ----
__global__ __launch_bounds__(256) void k_softmax(const float* __restrict__ xs_mask,
                                                 float* __restrict__ out) {
    __shared__ float red[256];
    int b = blockIdx.x;
    int tid = threadIdx.x;
    float loc[8];
    float m = -1e30f;
#pragma unroll
    for (int i = 0; i < 8; i++) {
        loc[i] = g_score[(tid + i * 256) * B_DIM + b];
        m = fmaxf(m, loc[i]);
    }
    red[tid] = m;
    __syncthreads();
#pragma unroll
    for (int o = 128; o > 0; o >>= 1) {
        if (tid < o) red[tid] = fmaxf(red[tid], red[tid + o]);
        __syncthreads();
    }
    m = red[0];
    __syncthreads();
    float e[8];
    float s = 0.0f;
#pragma unroll
    for (int i = 0; i < 8; i++) {
        e[i] = __expf(loc[i] - m) * xs_mask[(tid + i * 256) * B_DIM + b];
        s += e[i];
    }
    red[tid] = s;
    __syncthreads();
#pragma unroll
    for (int o = 128; o > 0; o >>= 1) {
        if (tid < o) red[tid] += red[tid + o];
        __syncthreads();
    }
    float inv = 1.0f / red[0];
#pragma unroll
    for (int i = 0; i < 8; i++) out[(tid + i * 256) * B_DIM + b] = e[i] * inv;
}

// ---- Kernel 4: partial attend sums. grid (N_SPLIT, B); block 256 thr, 4 floats each ----
__global__ __launch_bounds__(256) void k_attend(const float* __restrict__ xs_h,
                                                const float* __restrict__ e_out) {
    __shared__ float sw[L_PER_SPLIT];
    int s = blockIdx.x, b = blockIdx.y;
    int l0 = s * L_PER_SPLIT;
    if (threadIdx.x < L_PER_SPLIT)
        sw[threadIdx.x] = e_out[(l0 + threadIdx.x) * B_DIM + b];
    __syncthreads();
    float4 acc = make_float4(0.f, 0.f, 0.f, 0.f);
    const float4* base = (const float4*)xs_h;
    size_t idx = ((size_t)(l0 * B_DIM + b)) * (D_ENC / 4) + threadIdx.x;
#pragma unroll 4
    for (int i = 0; i < L_PER_SPLIT; i++) {
        float4 v = base[idx];
        float w = sw[i];
        acc.x = fmaf(w, v.x, acc.x);
        acc.y = fmaf(w, v.y, acc.y);
        acc.z = fmaf(w, v.z, acc.z);
        acc.w = fmaf(w, v.w, acc.w);
        idx += (size_t)B_DIM * (D_ENC / 4);
    }
    ((float4*)g_partial)[((s * B_DIM + b) * (D_ENC / 4)) + threadIdx.x] = acc;
}

// ---- Kernel 5: reduce partials -> attend[b,d] at out + L*B ----
__global__ __launch_bounds__(256) void k_reduce(float* __restrict__ attend_out) {
    int b = blockIdx.x;
    int t = threadIdx.x;   // float4 index within row (0..255)
    float4 acc = make_float4(0.f, 0.f, 0.f, 0.f);
#pragma unroll
    for (int s = 0; s < N_SPLIT; s++) {
        float4 v = ((const float4*)g_partial)[((s * B_DIM + b) * (D_ENC / 4)) + t];
        acc.x += v.x; acc.y += v.y; acc.z += v.z; acc.w += v.w;
    }
    ((float4*)attend_out)[b * (D_ENC / 4) + t] = acc;
}

extern "C" void kernel_launch(void* const* d_in, const int* in_sizes, int n_in,
                              void* d_out, int out_size) {
    const float* s_tm1   = (const float*)d_in[0];
    const float* xs_h    = (const float*)d_in[1];
    const float* uh      = (const float*)d_in[2];
    const float* xs_mask = (const float*)d_in[3];
    const float* sa_w    = (const float*)d_in[4];
    const float* sa_b    = (const float*)d_in[5];
    const float* a1_w    = (const float*)d_in[6];
    const float* a1_b    = (const float*)d_in[7];
    float* out = (float*)d_out;

    k_proj<<<4096, 256>>>(s_tm1, sa_w, sa_b);
    dim3 g2(L_DIM / 8, B_DIM);
    k_score<<<g2, 256>>>(uh, a1_w, a1_b);
    k_softmax<<<B_DIM, 256>>>(xs_mask, out);
    dim3 g4(N_SPLIT, B_DIM);
    k_attend<<<g4, 256>>>(xs_h, out);
    k_reduce<<<B_DIM, 256>>>(out + L_DIM * B_DIM);
}

// round 3
// speedup vs baseline: 1.0657x; 1.0657x over previous
#include <cuda_runtime.h>
#include <cstdint>

#define L_DIM 2048
#define B_DIM 64
#define D_DEC 1024
#define D_ALIGN 512
#define D_ENC 1024
#define N_SPLIT 16           // L splits for attend partials
#define L_PER_SPLIT (L_DIM / N_SPLIT)   // 128

// ---- scratch (no allocations allowed) ----
__device__ float g_proj[B_DIM * D_ALIGN];            // 128 KB
__device__ float g_score[L_DIM * B_DIM];             // 512 KB
__device__ float g_partial[N_SPLIT * B_DIM * D_ENC]; // 4 MB

__device__ __forceinline__ float tanh_approx(float x) {
    float y;
    asm("tanh.approx.f32 %0, %1;" : "=f"(y) : "f"(x));
    return y;
}

__device__ __forceinline__ float4 ldcs4(const float4* p) {
    float4 v;
    asm("ld.global.cs.v4.f32 {%0,%1,%2,%3}, [%4];"
        : "=f"(v.x), "=f"(v.y), "=f"(v.z), "=f"(v.w) : "l"(p));
    return v;
}

// ---- Kernel 1: proj = s_tm1 @ sa_w.T + sa_b, tiled 8a x 8b per block ----
// grid (64, 8): x = a-tile, y = b-tile. 256 threads = 8 warps, warp w -> a row.
__global__ __launch_bounds__(256) void k_proj(const float* __restrict__ s_tm1,
                                              const float* __restrict__ sa_w,
                                              const float* __restrict__ sa_b) {
    __shared__ float4 s_s[8][D_DEC / 4];   // 8 b-rows of s_tm1, 32 KB
    int atile = blockIdx.x, btile = blockIdx.y;
    for (int i = threadIdx.x; i < 8 * (D_DEC / 4); i += 256) {
        int bb = i >> 8, idx = i & 255;
        s_s[bb][idx] = ((const float4*)(s_tm1 + (size_t)(btile * 8 + bb) * D_DEC))[idx];
    }
    __syncthreads();
    int warp = threadIdx.x >> 5, lane = threadIdx.x & 31;
    int a = atile * 8 + warp;
    const float4* wr = (const float4*)(sa_w + (size_t)a * D_DEC);
    float acc[8] = {0.f, 0.f, 0.f, 0.f, 0.f, 0.f, 0.f, 0.f};
#pragma unroll
    for (int it = 0; it < 8; it++) {
        float4 w4 = wr[lane + it * 32];
#pragma unroll
        for (int bb = 0; bb < 8; bb++) {
            float4 s4 = s_s[bb][lane + it * 32];
            acc[bb] = fmaf(w4.x, s4.x, acc[bb]);
            acc[bb] = fmaf(w4.y, s4.y, acc[bb]);
            acc[bb] = fmaf(w4.z, s4.z, acc[bb]);
            acc[bb] = fmaf(w4.w, s4.w, acc[bb]);
        }
    }
    float bias = sa_b[a];
#pragma unroll
    for (int bb = 0; bb < 8; bb++) {
        float v = acc[bb];
#pragma unroll
        for (int o = 16; o > 0; o >>= 1) v += __shfl_xor_sync(0xFFFFFFFFu, v, o);
        if (lane == 0) g_proj[(btile * 8 + bb) * D_ALIGN + a] = v + bias;
    }
}

// ---- Kernel 2: score[l,b] = sum_a tanh(proj[b,a]+uh[l,b,a])*a1_w[a] + a1_b ----
__global__ __launch_bounds__(256) void k_score(const float* __restrict__ uh,
                                               const float* __restrict__ a1_w,
                                               const float* __restrict__ a1_b) {
    __shared__ float4 s_proj[D_ALIGN / 4];
    __shared__ float4 s_w[D_ALIGN / 4];
    int b = blockIdx.y;
    for (int i = threadIdx.x; i < D_ALIGN / 4; i += 256) {
        s_proj[i] = ((const float4*)(g_proj + b * D_ALIGN))[i];
        s_w[i] = ((const float4*)a1_w)[i];
    }
    __syncthreads();
    int warp = threadIdx.x >> 5, lane = threadIdx.x & 31;
    int l = blockIdx.x * 8 + warp;
    const float4* row = (const float4*)(uh + ((size_t)(l * B_DIM + b)) * D_ALIGN);
    float sum = 0.0f;
#pragma unroll
    for (int it = 0; it < 4; it++) {
        int a4 = lane + it * 32;
        float4 u = ldcs4(row + a4);
        float4 p = s_proj[a4];
        float4 w = s_w[a4];
        sum = fmaf(tanh_approx(p.x + u.x), w.x, sum);
        sum = fmaf(tanh_approx(p.y + u.y), w.y, sum);
        sum = fmaf(tanh_approx(p.z + u.z), w.z, sum);
        sum = fmaf(tanh_approx(p.w + u.w), w.w, sum);
    }
#pragma unroll
    for (int o = 16; o > 0; o >>= 1) sum += __shfl_xor_sync(0xFFFFFFFFu, sum, o);
    if (lane == 0) g_score[l * B_DIM + b] = sum + a1_b[0];
}

// ---- Kernel 3: masked softmax over L per column b; writes e_ij to out[0:L*B] ----
__global__ __launch_bounds__(256) void k_softmax(const float* __restrict__ xs_mask,
                                                 float* __restrict__ out) {
    __shared__ float red[256];
    int b = blockIdx.x;
    int tid = threadIdx.x;
    float loc[8];
    float m = -1e30f;
#pragma unroll
    for (int i = 0; i < 8; i++) {
        loc[i] = g_score[(tid + i * 256) * B_DIM + b];
        m = fmaxf(m, loc[i]);
    }
    red[tid] = m;
    __syncthreads();
#pragma unroll
    for (int o = 128; o > 0; o >>= 1) {
        if (tid < o) red[tid] = fmaxf(red[tid], red[tid + o]);
        __syncthreads();
    }
    m = red[0];
    __syncthreads();
    float e[8];
    float s = 0.0f;
#pragma unroll
    for (int i = 0; i < 8; i++) {
        e[i] = __expf(loc[i] - m) * xs_mask[(tid + i * 256) * B_DIM + b];
        s += e[i];
    }
    red[tid] = s;
    __syncthreads();
#pragma unroll
    for (int o = 128; o > 0; o >>= 1) {
        if (tid < o) red[tid] += red[tid + o];
        __syncthreads();
    }
    float inv = 1.0f / red[0];
#pragma unroll
    for (int i = 0; i < 8; i++) out[(tid + i * 256) * B_DIM + b] = e[i] * inv;
}

// ---- Kernel 4: partial attend sums. grid (N_SPLIT, B); block 256 thr, 4 floats each ----
__global__ __launch_bounds__(256) void k_attend(const float* __restrict__ xs_h,
                                                const float* __restrict__ e_out) {
    __shared__ float sw[L_PER_SPLIT];
    int s = blockIdx.x, b = blockIdx.y;
    int l0 = s * L_PER_SPLIT;
    if (threadIdx.x < L_PER_SPLIT)
        sw[threadIdx.x] = e_out[(l0 + threadIdx.x) * B_DIM + b];
    __syncthreads();
    float4 acc = make_float4(0.f, 0.f, 0.f, 0.f);
    const float4* base = (const float4*)xs_h;
    size_t idx = ((size_t)(l0 * B_DIM + b)) * (D_ENC / 4) + threadIdx.x;
#pragma unroll 4
    for (int i = 0; i < L_PER_SPLIT; i++) {
        float4 v = ldcs4(base + idx);
        float w = sw[i];
        acc.x = fmaf(w, v.x, acc.x);
        acc.y = fmaf(w, v.y, acc.y);
        acc.z = fmaf(w, v.z, acc.z);
        acc.w = fmaf(w, v.w, acc.w);
        idx += (size_t)B_DIM * (D_ENC / 4);
    }
    ((float4*)g_partial)[((s * B_DIM + b) * (D_ENC / 4)) + threadIdx.x] = acc;
}

// ---- Kernel 5: reduce partials -> attend[b,d] at out + L*B ----
__global__ __launch_bounds__(256) void k_reduce(float* __restrict__ attend_out) {
    int b = blockIdx.x;
    int t = threadIdx.x;   // float4 index within row (0..255)
    float4 acc = make_float4(0.f, 0.f, 0.f, 0.f);
#pragma unroll
    for (int s = 0; s < N_SPLIT; s++) {
        float4 v = ((const float4*)g_partial)[((s * B_DIM + b) * (D_ENC / 4)) + t];
        acc.x += v.x; acc.y += v.y; acc.z += v.z; acc.w += v.w;
    }
    ((float4*)attend_out)[b * (D_ENC / 4) + t] = acc;
}

extern "C" void kernel_launch(void* const* d_in, const int* in_sizes, int n_in,
                              void* d_out, int out_size) {
    const float* s_tm1   = (const float*)d_in[0];
    const float* xs_h    = (const float*)d_in[1];
    const float* uh      = (const float*)d_in[2];
    const float* xs_mask = (const float*)d_in[3];
    const float* sa_w    = (const float*)d_in[4];
    const float* sa_b    = (const float*)d_in[5];
    const float* a1_w    = (const float*)d_in[6];
    const float* a1_b    = (const float*)d_in[7];
    float* out = (float*)d_out;

    dim3 g1(64, 8);
    k_proj<<<g1, 256>>>(s_tm1, sa_w, sa_b);
    dim3 g2(L_DIM / 8, B_DIM);
    k_score<<<g2, 256>>>(uh, a1_w, a1_b);
    k_softmax<<<B_DIM, 256>>>(xs_mask, out);
    dim3 g4(N_SPLIT, B_DIM);
    k_attend<<<g4, 256>>>(xs_h, out);
    k_reduce<<<B_DIM, 256>>>(out + L_DIM * B_DIM);
}